// round 2
// baseline (speedup 1.0000x reference)
#include <cuda_runtime.h>

#define N_NODES 100000
#define N_EDGES 800000
#define C 128

// Allocation-free scratch
__device__ float g_s[N_NODES];          // x_0[i] . att[:C]
__device__ float g_t[N_NODES];          // x_0[i] . att[C:]
__device__ int          g_idx_is64;     // 1 if indices are int64
__device__ unsigned int g_bar;          // grid-barrier arrive counter
__device__ unsigned int g_done;         // post-phase counter for reset

__global__ void __launch_bounds__(256, 8) fused_kernel(
    const float* __restrict__ x, const void* __restrict__ src,
    const void* __restrict__ tgt, const float* __restrict__ att,
    float* __restrict__ out)
{
    const int tid  = threadIdx.x;
    const int lane = tid & 31;
    const int warpsPerBlock = blockDim.x >> 5;
    const int globalWarp = blockIdx.x * warpsPerBlock + (tid >> 5);
    const int totalWarps = gridDim.x * warpsPerBlock;

    // --- inline idx-dtype detect (block 0, thread 0); int64 values < 2^31
    // have all-zero high words; 64 zero odd words from random int32 ~ impossible.
    if (blockIdx.x == 0 && tid == 0) {
        const unsigned int* s32 = (const unsigned int*)src;
        unsigned int acc = 0;
        #pragma unroll
        for (int i = 0; i < 64; ++i) acc |= s32[2 * i + 1];
        g_idx_is64 = (acc == 0u) ? 1 : 0;
    }

    // --- phase 1: per-node dot products (warp per node, weights in regs)
    const float4 ws = reinterpret_cast<const float4*>(att)[lane];
    const float4 wt = reinterpret_cast<const float4*>(att + C)[lane];
    for (int n = globalWarp; n < N_NODES; n += totalWarps) {
        const float4 xv = reinterpret_cast<const float4*>(x + (size_t)n * C)[lane];
        float s = xv.x * ws.x + xv.y * ws.y + xv.z * ws.z + xv.w * ws.w;
        float t = xv.x * wt.x + xv.y * wt.y + xv.z * wt.z + xv.w * wt.w;
        #pragma unroll
        for (int o = 16; o > 0; o >>= 1) {
            s += __shfl_xor_sync(0xffffffffu, s, o);
            t += __shfl_xor_sync(0xffffffffu, t, o);
        }
        if (lane == 0) { g_s[n] = s; g_t[n] = t; }
    }

    // --- grid barrier (grid sized to one resident wave by the launcher)
    __syncthreads();
    if (tid == 0) {
        __threadfence();
        atomicAdd(&g_bar, 1u);
        while (*(volatile unsigned int*)&g_bar < gridDim.x) __nanosleep(64);
        __threadfence();
    }
    __syncthreads();

    const int is64 = g_idx_is64;

    // --- phase 2: edges, 4 per thread (128-bit index loads, float4 store)
    const int nQuads  = N_EDGES / 4;              // 800000 % 4 == 0
    const int gthread = blockIdx.x * blockDim.x + tid;
    const int gstride = gridDim.x * blockDim.x;
    for (int q = gthread; q < nQuads; q += gstride) {
        float4 r;
        if (is64) {
            const longlong2* s2 = (const longlong2*)src;
            const longlong2* t2 = (const longlong2*)tgt;
            longlong2 sa = s2[2 * q],     ta = t2[2 * q];
            longlong2 sb = s2[2 * q + 1], tb = t2[2 * q + 1];
            r.x = fmaxf(g_s[(int)sa.x] + g_t[(int)ta.x], 0.0f);
            r.y = fmaxf(g_s[(int)sa.y] + g_t[(int)ta.y], 0.0f);
            r.z = fmaxf(g_s[(int)sb.x] + g_t[(int)tb.x], 0.0f);
            r.w = fmaxf(g_s[(int)sb.y] + g_t[(int)tb.y], 0.0f);
        } else {
            const int4 si = ((const int4*)src)[q];
            const int4 ti = ((const int4*)tgt)[q];
            r.x = fmaxf(g_s[si.x] + g_t[ti.x], 0.0f);
            r.y = fmaxf(g_s[si.y] + g_t[ti.y], 0.0f);
            r.z = fmaxf(g_s[si.z] + g_t[ti.z], 0.0f);
            r.w = fmaxf(g_s[si.w] + g_t[ti.w], 0.0f);
        }
        reinterpret_cast<float4*>(out)[q] = r;
    }

    // --- reset barrier state for the next graph replay.
    // Safe: the last g_done arrival implies every block already exited the
    // g_bar spin, so zeroing g_bar cannot strand a spinner.
    __syncthreads();
    if (tid == 0) {
        unsigned int v = atomicAdd(&g_done, 1u);
        if (v == gridDim.x - 1) { g_bar = 0u; g_done = 0u; }
    }
}

extern "C" void kernel_launch(void* const* d_in, const int* in_sizes, int n_in,
                              void* d_out, int out_size) {
    const float* x_0 = (const float*)d_in[0];
    const void*  src = d_in[1];
    const void*  tgt = d_in[2];
    const float* att = (const float*)d_in[3];
    float* out = (float*)d_out;

    int dev = 0;
    cudaGetDevice(&dev);
    int sms = 0;
    cudaDeviceGetAttribute(&sms, cudaDevAttrMultiProcessorCount, dev);
    int blocksPerSM = 0;
    cudaOccupancyMaxActiveBlocksPerMultiprocessor(&blocksPerSM, fused_kernel, 256, 0);
    if (blocksPerSM < 1) blocksPerSM = 1;
    if (sms < 1) sms = 1;
    int grid = sms * blocksPerSM;          // exactly one resident wave

    fused_kernel<<<grid, 256>>>(x_0, src, tgt, att, out);
}

// round 3
// speedup vs baseline: 1.2590x; 1.2590x over previous
#include <cuda_runtime.h>

#define N_NODES 100000
#define N_EDGES 800000
#define C 128

// Allocation-free scratch: per-node dot products (16B-aligned for float4 stores)
__device__ __align__(16) float g_s[N_NODES];   // x_0[i] . att[:C]
__device__ __align__(16) float g_t[N_NODES];   // x_0[i] . att[C:]
__device__ int g_idx_is64;                     // 1 if indices are int64

// ---------------------------------------------------------------------------
// Node kernel: warp handles 4 consecutive nodes (MLP=4 on the row loads,
// 8 interleaved shuffle-reduce chains). 100000 nodes = 25000 warps * 4.
// Block 0 thread 0 also runs the index-dtype detect (int64 values < 2^31
// have all-zero high words; 64 zero odd words from random int32 ~ impossible).
// ---------------------------------------------------------------------------
__global__ void __launch_bounds__(256) node_kernel(
    const float* __restrict__ x, const float* __restrict__ att,
    const unsigned int* __restrict__ src32)
{
    if (blockIdx.x == 0 && threadIdx.x == 0) {
        unsigned int acc = 0;
        #pragma unroll
        for (int i = 0; i < 64; ++i) acc |= src32[2 * i + 1];
        g_idx_is64 = (acc == 0u) ? 1 : 0;
    }

    const int lane = threadIdx.x & 31;
    const int warp = (blockIdx.x * blockDim.x + threadIdx.x) >> 5;  // 0..24999
    const int n0 = warp * 4;
    if (n0 >= N_NODES) return;

    const float4 ws = reinterpret_cast<const float4*>(att)[lane];
    const float4 wt = reinterpret_cast<const float4*>(att + C)[lane];

    // 4 independent 128-bit row loads in flight
    const float4* xr = reinterpret_cast<const float4*>(x + (size_t)n0 * C);
    const float4 x0 = xr[lane];
    const float4 x1 = xr[32 + lane];
    const float4 x2 = xr[64 + lane];
    const float4 x3 = xr[96 + lane];

    float s0 = x0.x*ws.x + x0.y*ws.y + x0.z*ws.z + x0.w*ws.w;
    float s1 = x1.x*ws.x + x1.y*ws.y + x1.z*ws.z + x1.w*ws.w;
    float s2 = x2.x*ws.x + x2.y*ws.y + x2.z*ws.z + x2.w*ws.w;
    float s3 = x3.x*ws.x + x3.y*ws.y + x3.z*ws.z + x3.w*ws.w;
    float t0 = x0.x*wt.x + x0.y*wt.y + x0.z*wt.z + x0.w*wt.w;
    float t1 = x1.x*wt.x + x1.y*wt.y + x1.z*wt.z + x1.w*wt.w;
    float t2 = x2.x*wt.x + x2.y*wt.y + x2.z*wt.z + x2.w*wt.w;
    float t3 = x3.x*wt.x + x3.y*wt.y + x3.z*wt.z + x3.w*wt.w;

    // 8 independent butterfly chains — latency overlaps across chains
    #pragma unroll
    for (int o = 16; o > 0; o >>= 1) {
        s0 += __shfl_xor_sync(0xffffffffu, s0, o);
        s1 += __shfl_xor_sync(0xffffffffu, s1, o);
        s2 += __shfl_xor_sync(0xffffffffu, s2, o);
        s3 += __shfl_xor_sync(0xffffffffu, s3, o);
        t0 += __shfl_xor_sync(0xffffffffu, t0, o);
        t1 += __shfl_xor_sync(0xffffffffu, t1, o);
        t2 += __shfl_xor_sync(0xffffffffu, t2, o);
        t3 += __shfl_xor_sync(0xffffffffu, t3, o);
    }

    if (lane == 0) {
        *reinterpret_cast<float4*>(g_s + n0) = make_float4(s0, s1, s2, s3);
        *reinterpret_cast<float4*>(g_t + n0) = make_float4(t0, t1, t2, t3);
    }
}

// ---------------------------------------------------------------------------
// Edge kernel: 8 edges/thread. Index loads batched (128-bit), then 16
// independent L2-resident gathers outstanding, then 2 float4 stores.
// 800000 edges = 100000 threads * 8.
// ---------------------------------------------------------------------------
__global__ void __launch_bounds__(256) edge_kernel(
    const void* __restrict__ src, const void* __restrict__ tgt,
    float* __restrict__ out)
{
    const int t = blockIdx.x * blockDim.x + threadIdx.x;
    if (t >= N_EDGES / 8) return;

    int si[8], ti[8];
    if (g_idx_is64) {
        const longlong2* s2 = reinterpret_cast<const longlong2*>(src) + t * 4;
        const longlong2* t2 = reinterpret_cast<const longlong2*>(tgt) + t * 4;
        longlong2 a0 = s2[0], a1 = s2[1], a2 = s2[2], a3 = s2[3];
        longlong2 b0 = t2[0], b1 = t2[1], b2 = t2[2], b3 = t2[3];
        si[0] = (int)a0.x; si[1] = (int)a0.y; si[2] = (int)a1.x; si[3] = (int)a1.y;
        si[4] = (int)a2.x; si[5] = (int)a2.y; si[6] = (int)a3.x; si[7] = (int)a3.y;
        ti[0] = (int)b0.x; ti[1] = (int)b0.y; ti[2] = (int)b1.x; ti[3] = (int)b1.y;
        ti[4] = (int)b2.x; ti[5] = (int)b2.y; ti[6] = (int)b3.x; ti[7] = (int)b3.y;
    } else {
        const int4* s4 = reinterpret_cast<const int4*>(src) + t * 2;
        const int4* t4 = reinterpret_cast<const int4*>(tgt) + t * 2;
        int4 a0 = s4[0], a1 = s4[1];
        int4 b0 = t4[0], b1 = t4[1];
        si[0] = a0.x; si[1] = a0.y; si[2] = a0.z; si[3] = a0.w;
        si[4] = a1.x; si[5] = a1.y; si[6] = a1.z; si[7] = a1.w;
        ti[0] = b0.x; ti[1] = b0.y; ti[2] = b0.z; ti[3] = b0.w;
        ti[4] = b1.x; ti[5] = b1.y; ti[6] = b1.z; ti[7] = b1.w;
    }

    // 16 independent gathers in flight (L2-resident 800KB tables)
    float sv[8], tv[8];
    #pragma unroll
    for (int k = 0; k < 8; ++k) sv[k] = __ldg(g_s + si[k]);
    #pragma unroll
    for (int k = 0; k < 8; ++k) tv[k] = __ldg(g_t + ti[k]);

    float4 r0, r1;
    r0.x = fmaxf(sv[0] + tv[0], 0.0f);
    r0.y = fmaxf(sv[1] + tv[1], 0.0f);
    r0.z = fmaxf(sv[2] + tv[2], 0.0f);
    r0.w = fmaxf(sv[3] + tv[3], 0.0f);
    r1.x = fmaxf(sv[4] + tv[4], 0.0f);
    r1.y = fmaxf(sv[5] + tv[5], 0.0f);
    r1.z = fmaxf(sv[6] + tv[6], 0.0f);
    r1.w = fmaxf(sv[7] + tv[7], 0.0f);

    float4* o4 = reinterpret_cast<float4*>(out) + t * 2;
    o4[0] = r0;
    o4[1] = r1;
}

extern "C" void kernel_launch(void* const* d_in, const int* in_sizes, int n_in,
                              void* d_out, int out_size) {
    const float* x_0 = (const float*)d_in[0];
    const void*  src = d_in[1];
    const void*  tgt = d_in[2];
    const float* att = (const float*)d_in[3];
    float* out = (float*)d_out;

    // 25000 warps, 8 warps/block -> 3125 blocks (exact)
    node_kernel<<<3125, 256>>>(x_0, att, (const unsigned int*)src);

    // 100000 threads, 8 edges each -> 391 blocks
    edge_kernel<<<(N_EDGES / 8 + 255) / 256, 256>>>(src, tgt, out);
}

// round 4
// speedup vs baseline: 1.3933x; 1.1067x over previous
#include <cuda_runtime.h>

#define N_NODES 100000
#define N_EDGES 800000
#define C 128

// Allocation-free scratch: per-node dot products (16B-aligned for float4 stores)
__device__ __align__(16) float g_s[N_NODES];   // x_0[i] . att[:C]
__device__ __align__(16) float g_t[N_NODES];   // x_0[i] . att[C:]
__device__ int g_idx_is64;                     // 1 if indices are int64

// ---------------------------------------------------------------------------
// Node kernel (unchanged — measured at ~5.7 TB/s, near LTS cap):
// warp handles 4 consecutive nodes (MLP=4 row loads, 8 interleaved
// shuffle-reduce chains). Block 0 thread 0 runs the index-dtype detect.
// ---------------------------------------------------------------------------
__global__ void __launch_bounds__(256) node_kernel(
    const float* __restrict__ x, const float* __restrict__ att,
    const unsigned int* __restrict__ src32)
{
    if (blockIdx.x == 0 && threadIdx.x == 0) {
        unsigned int acc = 0;
        #pragma unroll
        for (int i = 0; i < 64; ++i) acc |= src32[2 * i + 1];
        g_idx_is64 = (acc == 0u) ? 1 : 0;
    }

    const int lane = threadIdx.x & 31;
    const int warp = (blockIdx.x * blockDim.x + threadIdx.x) >> 5;  // 0..24999
    const int n0 = warp * 4;
    if (n0 >= N_NODES) return;

    const float4 ws = reinterpret_cast<const float4*>(att)[lane];
    const float4 wt = reinterpret_cast<const float4*>(att + C)[lane];

    const float4* xr = reinterpret_cast<const float4*>(x + (size_t)n0 * C);
    const float4 x0 = xr[lane];
    const float4 x1 = xr[32 + lane];
    const float4 x2 = xr[64 + lane];
    const float4 x3 = xr[96 + lane];

    float s0 = x0.x*ws.x + x0.y*ws.y + x0.z*ws.z + x0.w*ws.w;
    float s1 = x1.x*ws.x + x1.y*ws.y + x1.z*ws.z + x1.w*ws.w;
    float s2 = x2.x*ws.x + x2.y*ws.y + x2.z*ws.z + x2.w*ws.w;
    float s3 = x3.x*ws.x + x3.y*ws.y + x3.z*ws.z + x3.w*ws.w;
    float t0 = x0.x*wt.x + x0.y*wt.y + x0.z*wt.z + x0.w*wt.w;
    float t1 = x1.x*wt.x + x1.y*wt.y + x1.z*wt.z + x1.w*wt.w;
    float t2 = x2.x*wt.x + x2.y*wt.y + x2.z*wt.z + x2.w*wt.w;
    float t3 = x3.x*wt.x + x3.y*wt.y + x3.z*wt.z + x3.w*wt.w;

    #pragma unroll
    for (int o = 16; o > 0; o >>= 1) {
        s0 += __shfl_xor_sync(0xffffffffu, s0, o);
        s1 += __shfl_xor_sync(0xffffffffu, s1, o);
        s2 += __shfl_xor_sync(0xffffffffu, s2, o);
        s3 += __shfl_xor_sync(0xffffffffu, s3, o);
        t0 += __shfl_xor_sync(0xffffffffu, t0, o);
        t1 += __shfl_xor_sync(0xffffffffu, t1, o);
        t2 += __shfl_xor_sync(0xffffffffu, t2, o);
        t3 += __shfl_xor_sync(0xffffffffu, t3, o);
    }

    if (lane == 0) {
        *reinterpret_cast<float4*>(g_s + n0) = make_float4(s0, s1, s2, s3);
        *reinterpret_cast<float4*>(g_t + n0) = make_float4(t0, t1, t2, t3);
    }
}

// ---------------------------------------------------------------------------
// Edge kernel: 2 edges/thread, 400K threads (TLP-first rebalance).
// Per thread: one vectorized index load per array, 4 independent L2-hit
// gathers in flight, one float2 store. 800000 = 400000 * 2 exactly.
// ---------------------------------------------------------------------------
__global__ void __launch_bounds__(256) edge_kernel(
    const void* __restrict__ src, const void* __restrict__ tgt,
    float* __restrict__ out)
{
    const int t = blockIdx.x * blockDim.x + threadIdx.x;
    if (t >= N_EDGES / 2) return;

    int si0, si1, ti0, ti1;
    if (g_idx_is64) {
        const longlong2 a = reinterpret_cast<const longlong2*>(src)[t];
        const longlong2 b = reinterpret_cast<const longlong2*>(tgt)[t];
        si0 = (int)a.x; si1 = (int)a.y;
        ti0 = (int)b.x; ti1 = (int)b.y;
    } else {
        const int2 a = reinterpret_cast<const int2*>(src)[t];
        const int2 b = reinterpret_cast<const int2*>(tgt)[t];
        si0 = a.x; si1 = a.y;
        ti0 = b.x; ti1 = b.y;
    }

    // 4 independent gathers outstanding
    const float s0 = __ldg(g_s + si0);
    const float s1 = __ldg(g_s + si1);
    const float v0 = __ldg(g_t + ti0);
    const float v1 = __ldg(g_t + ti1);

    float2 r;
    r.x = fmaxf(s0 + v0, 0.0f);
    r.y = fmaxf(s1 + v1, 0.0f);
    reinterpret_cast<float2*>(out)[t] = r;
}

extern "C" void kernel_launch(void* const* d_in, const int* in_sizes, int n_in,
                              void* d_out, int out_size) {
    const float* x_0 = (const float*)d_in[0];
    const void*  src = d_in[1];
    const void*  tgt = d_in[2];
    const float* att = (const float*)d_in[3];
    float* out = (float*)d_out;

    // 25000 warps, 8 warps/block -> 3125 blocks (exact)
    node_kernel<<<3125, 256>>>(x_0, att, (const unsigned int*)src);

    // 400000 threads, 2 edges each -> 1563 blocks
    edge_kernel<<<(N_EDGES / 2 + 255) / 256, 256>>>(src, tgt, out);
}

// round 5
// speedup vs baseline: 1.4146x; 1.0152x over previous
#include <cuda_runtime.h>

#define N_NODES 100000
#define N_EDGES 800000
#define C 128

// Allocation-free scratch: per-node dot products (16B-aligned for float4 stores)
__device__ __align__(16) float g_s[N_NODES];   // x_0[i] . att[:C]
__device__ __align__(16) float g_t[N_NODES];   // x_0[i] . att[C:]
__device__ int g_idx_is64;                     // 1 if indices are int64

// ---------------------------------------------------------------------------
// Node kernel (unchanged — measured near DRAM roofline).
// ---------------------------------------------------------------------------
__global__ void __launch_bounds__(256) node_kernel(
    const float* __restrict__ x, const float* __restrict__ att,
    const unsigned int* __restrict__ src32)
{
    if (blockIdx.x == 0 && threadIdx.x == 0) {
        unsigned int acc = 0;
        #pragma unroll
        for (int i = 0; i < 64; ++i) acc |= src32[2 * i + 1];
        g_idx_is64 = (acc == 0u) ? 1 : 0;
    }

    const int lane = threadIdx.x & 31;
    const int warp = (blockIdx.x * blockDim.x + threadIdx.x) >> 5;  // 0..24999
    const int n0 = warp * 4;
    if (n0 >= N_NODES) return;

    const float4 ws = reinterpret_cast<const float4*>(att)[lane];
    const float4 wt = reinterpret_cast<const float4*>(att + C)[lane];

    const float4* xr = reinterpret_cast<const float4*>(x + (size_t)n0 * C);
    const float4 x0 = xr[lane];
    const float4 x1 = xr[32 + lane];
    const float4 x2 = xr[64 + lane];
    const float4 x3 = xr[96 + lane];

    float s0 = x0.x*ws.x + x0.y*ws.y + x0.z*ws.z + x0.w*ws.w;
    float s1 = x1.x*ws.x + x1.y*ws.y + x1.z*ws.z + x1.w*ws.w;
    float s2 = x2.x*ws.x + x2.y*ws.y + x2.z*ws.z + x2.w*ws.w;
    float s3 = x3.x*ws.x + x3.y*ws.y + x3.z*ws.z + x3.w*ws.w;
    float t0 = x0.x*wt.x + x0.y*wt.y + x0.z*wt.z + x0.w*wt.w;
    float t1 = x1.x*wt.x + x1.y*wt.y + x1.z*wt.z + x1.w*wt.w;
    float t2 = x2.x*wt.x + x2.y*wt.y + x2.z*wt.z + x2.w*wt.w;
    float t3 = x3.x*wt.x + x3.y*wt.y + x3.z*wt.z + x3.w*wt.w;

    #pragma unroll
    for (int o = 16; o > 0; o >>= 1) {
        s0 += __shfl_xor_sync(0xffffffffu, s0, o);
        s1 += __shfl_xor_sync(0xffffffffu, s1, o);
        s2 += __shfl_xor_sync(0xffffffffu, s2, o);
        s3 += __shfl_xor_sync(0xffffffffu, s3, o);
        t0 += __shfl_xor_sync(0xffffffffu, t0, o);
        t1 += __shfl_xor_sync(0xffffffffu, t1, o);
        t2 += __shfl_xor_sync(0xffffffffu, t2, o);
        t3 += __shfl_xor_sync(0xffffffffu, t3, o);
    }

    if (lane == 0) {
        *reinterpret_cast<float4*>(g_s + n0) = make_float4(s0, s1, s2, s3);
        *reinterpret_cast<float4*>(g_t + n0) = make_float4(t0, t1, t2, t3);
    }
}

// Predicated gather: lane executes the LDG only on its step (grp == k).
// Inline PTX guarantees a @p-predicated LDG (no BSSY/BSYNC branches, no
// re-merging), so each gather LDG has only 8 active lanes -> 8 wavefronts,
// and wavefronts from distinct LDGs interleave at the cross-LDG rate.
__device__ __forceinline__ float pred_gather(const float* addr, int grp, int k, float prev) {
    float v = prev;
    asm("{ .reg .pred p; setp.eq.s32 p, %1, %2; @p ld.global.nc.f32 %0, [%3]; }"
        : "+f"(v) : "r"(grp), "r"(k), "l"(addr));
    return v;
}

// ---------------------------------------------------------------------------
// Edge kernel: 2 edges/thread, each of the 4 gathers split into 4
// quarter-warp predicated LDGs (16 LDGs/thread-group, 8 active lanes each).
// ---------------------------------------------------------------------------
__global__ void __launch_bounds__(256) edge_kernel(
    const void* __restrict__ src, const void* __restrict__ tgt,
    float* __restrict__ out)
{
    const int t = blockIdx.x * blockDim.x + threadIdx.x;
    if (t >= N_EDGES / 2) return;

    int si0, si1, ti0, ti1;
    if (g_idx_is64) {
        const longlong2 a = reinterpret_cast<const longlong2*>(src)[t];
        const longlong2 b = reinterpret_cast<const longlong2*>(tgt)[t];
        si0 = (int)a.x; si1 = (int)a.y;
        ti0 = (int)b.x; ti1 = (int)b.y;
    } else {
        const int2 a = reinterpret_cast<const int2*>(src)[t];
        const int2 b = reinterpret_cast<const int2*>(tgt)[t];
        si0 = a.x; si1 = a.y;
        ti0 = b.x; ti1 = b.y;
    }

    const int grp = (threadIdx.x & 31) >> 3;   // lane group 0..3
    float s0 = 0.f, s1 = 0.f, v0 = 0.f, v1 = 0.f;
    #pragma unroll
    for (int k = 0; k < 4; ++k) {
        s0 = pred_gather(g_s + si0, grp, k, s0);
        s1 = pred_gather(g_s + si1, grp, k, s1);
        v0 = pred_gather(g_t + ti0, grp, k, v0);
        v1 = pred_gather(g_t + ti1, grp, k, v1);
    }

    float2 r;
    r.x = fmaxf(s0 + v0, 0.0f);
    r.y = fmaxf(s1 + v1, 0.0f);
    reinterpret_cast<float2*>(out)[t] = r;
}

extern "C" void kernel_launch(void* const* d_in, const int* in_sizes, int n_in,
                              void* d_out, int out_size) {
    const float* x_0 = (const float*)d_in[0];
    const void*  src = d_in[1];
    const void*  tgt = d_in[2];
    const float* att = (const float*)d_in[3];
    float* out = (float*)d_out;

    // 25000 warps, 8 warps/block -> 3125 blocks (exact)
    node_kernel<<<3125, 256>>>(x_0, att, (const unsigned int*)src);

    // 400000 threads, 2 edges each -> 1563 blocks
    edge_kernel<<<(N_EDGES / 2 + 255) / 256, 256>>>(src, tgt, out);
}